// round 14
// baseline (speedup 1.0000x reference)
#include <cuda_runtime.h>
#include <cuda_fp16.h>
#include <math.h>
#include <stdint.h>

#define BB 4
#define SS 2048
#define DM 768
#define NH 12
#define HD 64
#define DM3 2304
#define MR (BB*SS)

// ---------------- scratch ----------------
__device__ __half g_t1 [(size_t)MR*DM];
__device__ __half g_bh [(size_t)MR*DM];
__device__ __half g_qh [(size_t)MR*DM];   // [b*NH+h][s][64], pre-scaled 0.125*log2e
__device__ __half g_kh [(size_t)MR*DM];
__device__ __half g_vt [(size_t)MR*DM];   // [b*NH+h][64][2048]  (V^T)
__device__ __half g_av [(size_t)MR*DM];
__device__ __half g_hh [(size_t)MR*DM];   // hidden (f16 only)
__device__ __half g_wqT[(size_t)DM3*DM];
__device__ __half g_w1T[(size_t)DM*DM];
__device__ __half g_w2T[(size_t)DM*DM];

// ---------------- helpers ----------------
__device__ __forceinline__ uint32_t smem_u32(const void* p){
    uint32_t a;
    asm("{ .reg .u64 t; cvta.to.shared.u64 t, %1; cvt.u32.u64 %0, t; }" : "=r"(a) : "l"(p));
    return a;
}
#define CPA(dst, src) asm volatile("cp.async.cg.shared.global [%0], [%1], 16;" :: "r"((uint32_t)(dst)), "l"(src) : "memory")
#define CPA_COMMIT() asm volatile("cp.async.commit_group;" ::: "memory")
#define CPA_WAIT0() asm volatile("cp.async.wait_group 0;" ::: "memory")
#define CPA_WAIT1() asm volatile("cp.async.wait_group 1;" ::: "memory")

__device__ __forceinline__ uint32_t swz(uint32_t o){ return o ^ ((o >> 3) & 0x70); }

__device__ __forceinline__ void ldsm4(uint32_t &r0, uint32_t &r1, uint32_t &r2, uint32_t &r3, uint32_t a){
    asm volatile("ldmatrix.sync.aligned.m8n8.x4.shared.b16 {%0,%1,%2,%3}, [%4];"
                 : "=r"(r0), "=r"(r1), "=r"(r2), "=r"(r3) : "r"(a));
}
__device__ __forceinline__ void mma16816(float* c, uint32_t a0, uint32_t a1, uint32_t a2, uint32_t a3,
                                         uint32_t b0, uint32_t b1){
    asm volatile("mma.sync.aligned.m16n8k16.row.col.f32.f16.f16.f32 "
                 "{%0,%1,%2,%3}, {%4,%5,%6,%7}, {%8,%9}, {%0,%1,%2,%3};"
                 : "+f"(c[0]), "+f"(c[1]), "+f"(c[2]), "+f"(c[3])
                 : "r"(a0), "r"(a1), "r"(a2), "r"(a3), "r"(b0), "r"(b1));
}
__device__ __forceinline__ void mma16816h(uint32_t* c, uint32_t a0, uint32_t a1, uint32_t a2, uint32_t a3,
                                          uint32_t b0, uint32_t b1){
    asm volatile("mma.sync.aligned.m16n8k16.row.col.f16.f16.f16.f16 "
                 "{%0,%1}, {%2,%3,%4,%5}, {%6,%7}, {%0,%1};"
                 : "+r"(c[0]), "+r"(c[1])
                 : "r"(a0), "r"(a1), "r"(a2), "r"(a3), "r"(b0), "r"(b1));
}
__device__ __forceinline__ uint32_t pack2(float a, float b){
    __half2 h = __floats2half2_rn(a, b);
    return *(uint32_t*)&h;
}
#define EX2IP(r) asm("ex2.approx.f16x2 %0, %0;" : "+r"(r))

// ---------------- merged prep ----------------
#define PREP_CB 1024
#define PREP_TQ ((DM3/32)*(DM/32))   // 1728
#define PREP_T1 ((DM/32)*(DM/32))    // 576
#define PREP_TOTAL (PREP_CB + PREP_TQ + 2*PREP_T1)

__device__ __forceinline__ void transp_tile(const float* __restrict__ W, __half* __restrict__ T,
                                            int K, int N, int n0, int k0, float (*s)[33]){
    int j = threadIdx.x & 31, i0 = threadIdx.x >> 5;
    #pragma unroll
    for (int l = 0; l < 4; l++){ int i = i0 + l*8; s[i][j] = W[(size_t)(k0+i)*N + n0 + j]; }
    __syncthreads();
    #pragma unroll
    for (int l = 0; l < 4; l++){
        int i = i0 + l*8;
        T[(size_t)(n0+i)*K + k0 + j] = __float2half_rn(s[j][i]);
    }
}

__global__ __launch_bounds__(256)
void prep(const float4* __restrict__ base4, uint2* __restrict__ bh4,
          const float* __restrict__ Wqkv, __half* __restrict__ wqT,
          const float* __restrict__ W1,   __half* __restrict__ w1T,
          const float* __restrict__ W2,   __half* __restrict__ w2T)
{
    __shared__ float s[32][33];
    int b = blockIdx.x;
    if (b < PREP_CB){
        const int n4 = MR*DM/4;
        for (int i = b*256 + threadIdx.x; i < n4; i += PREP_CB*256){
            float4 v = base4[i];
            uint2 o = { pack2(v.x, v.y), pack2(v.z, v.w) };
            bh4[i] = o;
        }
    } else if (b < PREP_CB + PREP_TQ){
        int idx = b - PREP_CB;
        transp_tile(Wqkv, wqT, DM, DM3, (idx % (DM3/32))*32, (idx / (DM3/32))*32, s);
    } else if (b < PREP_CB + PREP_TQ + PREP_T1){
        int idx = b - PREP_CB - PREP_TQ;
        transp_tile(W1, w1T, DM, DM, (idx % (DM/32))*32, (idx / (DM/32))*32, s);
    } else {
        int idx = b - PREP_CB - PREP_TQ - PREP_T1;
        transp_tile(W2, w2T, DM, DM, (idx % (DM/32))*32, (idx / (DM/32))*32, s);
    }
}

// ---------------- GEMM: A[M][K]@B[N][K]^T + bias, fp32 accum, 128x128 tiles ----------------
// 3-stage cp.async pipeline, ONE barrier per K-chunk.
// MODE 0: C f16 [M][N].  MODE 1: fused QKV epilogue.
template<int N, int K, int MODE>
__global__ __launch_bounds__(256, 2)
void gemm_h(const __half* __restrict__ A, const __half* __restrict__ B,
            const float* __restrict__ bias, __half* __restrict__ C,
            __half* __restrict__ qh, __half* __restrict__ kh, __half* __restrict__ vt)
{
    extern __shared__ char sm[];
    const uint32_t sb = smem_u32(sm);
    const int tid = threadIdx.x, lane = tid & 31, wid = tid >> 5;
    const int wm = (wid & 1)*64, wn = (wid >> 1)*32;
    const int m0 = blockIdx.y*128, n0 = blockIdx.x*128;
    const int NC = K/64;

    float acc[4][4][4] = {};

    auto load = [&](int c, int s){
        uint32_t sa = sb + s*32768, sbm = sa + 16384;
        int k0 = c*64;
        #pragma unroll
        for (int l = 0; l < 4; l++){
            int idx = tid + l*256;
            int r = idx >> 3, c16 = idx & 7;
            uint32_t o = swz((uint32_t)(r*128 + c16*16));
            CPA(sa  + o, (const char*)(A + (size_t)(m0+r)*K + k0 + c16*8));
            CPA(sbm + o, (const char*)(B + (size_t)(n0+r)*K + k0 + c16*8));
        }
        CPA_COMMIT();
    };

    load(0, 0);
    load(1, 1);
    for (int c = 0; c < NC; c++){
        int s = c % 3;
        if (c+1 < NC) CPA_WAIT1(); else CPA_WAIT0();   // chunk c resident
        __syncthreads();                                // all warps done reading stage (c-1)%3
        if (c+2 < NC) load(c+2, (c+2) % 3);             // overwrite stage (c-1)%3
        uint32_t sa = sb + s*32768, sbm = sa + 16384;
        #pragma unroll
        for (int ks = 0; ks < 4; ks++){
            uint32_t a[4][4];
            #pragma unroll
            for (int mt = 0; mt < 4; mt++)
                ldsm4(a[mt][0], a[mt][1], a[mt][2], a[mt][3],
                      sa + swz((uint32_t)((wm + mt*16 + (lane & 15))*128 + (ks*16 + ((lane >> 4) << 3))*2)));
            #pragma unroll
            for (int np = 0; np < 2; np++){
                uint32_t b0, b1, b2, b3;
                int n  = wn + np*16 + ((lane >> 4) << 3) + (lane & 7);
                int kh2 = ks*16 + ((lane >> 3) & 1)*8;
                ldsm4(b0, b1, b2, b3, sbm + swz((uint32_t)(n*128 + kh2*2)));
                #pragma unroll
                for (int mt = 0; mt < 4; mt++){
                    mma16816(acc[mt][np*2],   a[mt][0], a[mt][1], a[mt][2], a[mt][3], b0, b1);
                    mma16816(acc[mt][np*2+1], a[mt][0], a[mt][1], a[mt][2], a[mt][3], b2, b3);
                }
            }
        }
    }
    __syncthreads();

    if (MODE == 0){
        #pragma unroll
        for (int mt = 0; mt < 4; mt++){
            int row = m0 + wm + mt*16 + (lane >> 2);
            #pragma unroll
            for (int nt = 0; nt < 4; nt++){
                int col = n0 + wn + nt*8 + 2*(lane & 3);
                float2 bi = *(const float2*)&bias[col];
                *(uint32_t*)&C[(size_t)row*N + col]     = pack2(acc[mt][nt][0] + bi.x, acc[mt][nt][1] + bi.y);
                *(uint32_t*)&C[(size_t)(row+8)*N + col] = pack2(acc[mt][nt][2] + bi.x, acc[mt][nt][3] + bi.y);
            }
        }
    } else {
        const int b  = m0 >> 11;
        const int s0 = m0 & 2047;
        const int region = n0 / DM;
        const int h0 = (n0 % DM) >> 6;
        if (region < 2){
            const float sc = (region == 0) ? 0.125f*1.44269504f : 1.f;
            __half* dst = (region == 0) ? qh : kh;
            #pragma unroll
            for (int mt = 0; mt < 4; mt++){
                int r = wm + mt*16 + (lane >> 2);
                #pragma unroll
                for (int nt = 0; nt < 4; nt++){
                    int cl = wn + nt*8 + 2*(lane & 3);
                    float2 bi = *(const float2*)&bias[n0 + cl];
                    int h = h0 + (cl >> 6), d = cl & 63;
                    size_t a0 = ((size_t)(b*NH + h)*SS + s0 + r)*64 + d;
                    *(uint32_t*)&dst[a0]        = pack2((acc[mt][nt][0]+bi.x)*sc, (acc[mt][nt][1]+bi.y)*sc);
                    *(uint32_t*)&dst[a0 + 8*64] = pack2((acc[mt][nt][2]+bi.x)*sc, (acc[mt][nt][3]+bi.y)*sc);
                }
            }
        } else {
            __half* st = (__half*)sm;
            #pragma unroll
            for (int mt = 0; mt < 4; mt++){
                int r = wm + mt*16 + (lane >> 2);
                #pragma unroll
                for (int nt = 0; nt < 4; nt++){
                    int cl = wn + nt*8 + 2*(lane & 3);
                    float2 bi = *(const float2*)&bias[n0 + cl];
                    st[(cl+0)*136 + r]     = __float2half_rn(acc[mt][nt][0] + bi.x);
                    st[(cl+1)*136 + r]     = __float2half_rn(acc[mt][nt][1] + bi.y);
                    st[(cl+0)*136 + r + 8] = __float2half_rn(acc[mt][nt][2] + bi.x);
                    st[(cl+1)*136 + r + 8] = __float2half_rn(acc[mt][nt][3] + bi.y);
                }
            }
            __syncthreads();
            #pragma unroll
            for (int l = 0; l < 8; l++){
                int idx = tid + l*256;
                int d = idx >> 4, rc = idx & 15;
                uint4 v = *(const uint4*)&st[d*136 + rc*8];
                int h = h0 + (d >> 6), dl = d & 63;
                *(uint4*)&vt[((size_t)(b*NH + h)*64 + dl)*SS + s0 + rc*8] = v;
            }
        }
    }
}

// ---------------- attention: CTA = (256-query tile, bh); 8 warps x 32 q-rows, f16 accum ----------------
__global__ __launch_bounds__(256, 2)
void attn_h(const __half* __restrict__ Q, const __half* __restrict__ Kh,
            const __half* __restrict__ Vt, __half* __restrict__ av)
{
    extern __shared__ char sm[];
    const uint32_t sb = smem_u32(sm);
    const uint32_t SQ = sb;            // 32KB (256 q rows)
    const uint32_t SK = sb + 32768;    // 2 x 16KB
    const uint32_t SV = sb + 65536;    // 2 x 16KB
    const int tid = threadIdx.x, lane = tid & 31, wid = tid >> 5;
    const int q0 = blockIdx.x*256, bh = blockIdx.y;
    const __half* Qp = Q  + (size_t)bh*SS*64 + (size_t)q0*64;
    const __half* Kp = Kh + (size_t)bh*SS*64;
    const __half* Vp = Vt + (size_t)bh*64*SS;

    #pragma unroll
    for (int l = 0; l < 8; l++){
        int idx = tid + l*256; int r = idx >> 3, c = idx & 7;
        CPA(SQ + swz((uint32_t)(r*128 + c*16)), (const char*)(Qp + r*64 + c*8));
    }
    #pragma unroll
    for (int l = 0; l < 4; l++){
        int idx = tid + l*256; int r = idx >> 3, c = idx & 7;
        CPA(SK + swz((uint32_t)(r*128 + c*16)), (const char*)(Kp + r*64 + c*8));
    }
    #pragma unroll
    for (int l = 0; l < 4; l++){
        int idx = tid + l*256; int d = idx >> 4, c = idx & 15;
        CPA(SV + (c >> 3)*8192 + swz((uint32_t)(d*128 + (c & 7)*16)), (const char*)(Vp + (size_t)d*SS + c*8));
    }
    CPA_COMMIT();

    uint32_t o16[2][8][2] = {};
    float rs[2][2] = {};
    uint32_t qf[2][4][4];

    for (int t = 0; t < 16; t++){
        int s = t & 1;
        if (t+1 < 16){
            const __half* Kn = Kp + (size_t)(t+1)*128*64;
            #pragma unroll
            for (int l = 0; l < 4; l++){
                int idx = tid + l*256; int r = idx >> 3, c = idx & 7;
                CPA(SK + (1-s)*16384 + swz((uint32_t)(r*128 + c*16)), (const char*)(Kn + r*64 + c*8));
            }
            #pragma unroll
            for (int l = 0; l < 4; l++){
                int idx = tid + l*256; int d = idx >> 4, c = idx & 15;
                CPA(SV + (1-s)*16384 + (c >> 3)*8192 + swz((uint32_t)(d*128 + (c & 7)*16)),
                    (const char*)(Vp + (size_t)d*SS + (t+1)*128 + c*8));
            }
            CPA_COMMIT();
            CPA_WAIT1();
        } else CPA_WAIT0();
        __syncthreads();

        if (t == 0){
            #pragma unroll
            for (int mt = 0; mt < 2; mt++)
                #pragma unroll
                for (int ks = 0; ks < 4; ks++)
                    ldsm4(qf[mt][ks][0], qf[mt][ks][1], qf[mt][ks][2], qf[mt][ks][3],
                          SQ + swz((uint32_t)((wid*32 + mt*16 + (lane & 15))*128 + (ks*16 + ((lane >> 4) << 3))*2)));
        }

        uint32_t sk = SK + s*16384, sv = SV + s*16384;
        __half2 rhA[2], rhB[2];
        rhA[0] = rhA[1] = rhB[0] = rhB[1] = __floats2half2_rn(0.f, 0.f);
        #pragma unroll
        for (int np = 0; np < 8; np++){
            uint32_t sc[2][2][2] = {};
            #pragma unroll
            for (int ks = 0; ks < 4; ks++){
                uint32_t b0, b1, b2, b3;
                int n  = np*16 + ((lane >> 4) << 3) + (lane & 7);
                int kh = ks*16 + ((lane >> 3) & 1)*8;
                ldsm4(b0, b1, b2, b3, sk + swz((uint32_t)(n*128 + kh*2)));
                #pragma unroll
                for (int mt = 0; mt < 2; mt++){
                    mma16816h(sc[mt][0], qf[mt][ks][0], qf[mt][ks][1], qf[mt][ks][2], qf[mt][ks][3], b0, b1);
                    mma16816h(sc[mt][1], qf[mt][ks][0], qf[mt][ks][1], qf[mt][ks][2], qf[mt][ks][3], b2, b3);
                }
            }
            #pragma unroll
            for (int mt = 0; mt < 2; mt++){
                EX2IP(sc[mt][0][0]); EX2IP(sc[mt][0][1]);
                EX2IP(sc[mt][1][0]); EX2IP(sc[mt][1][1]);
                rhA[mt] = __hadd2(rhA[mt], __hadd2(*(__half2*)&sc[mt][0][0], *(__half2*)&sc[mt][1][0]));
                rhB[mt] = __hadd2(rhB[mt], __hadd2(*(__half2*)&sc[mt][0][1], *(__half2*)&sc[mt][1][1]));
            }
            #pragma unroll
            for (int dp = 0; dp < 4; dp++){
                uint32_t b0, b1, b2, b3;
                int d   = dp*16 + ((lane >> 4) << 3) + (lane & 7);
                int key = np*16 + ((lane >> 3) & 1)*8;
                ldsm4(b0, b1, b2, b3, sv + (key >> 6)*8192 + swz((uint32_t)(d*128 + (key & 63)*2)));
                #pragma unroll
                for (int mt = 0; mt < 2; mt++){
                    mma16816h(o16[mt][dp*2],   sc[mt][0][0], sc[mt][0][1], sc[mt][1][0], sc[mt][1][1], b0, b1);
                    mma16816h(o16[mt][dp*2+1], sc[mt][0][0], sc[mt][0][1], sc[mt][1][0], sc[mt][1][1], b2, b3);
                }
            }
        }
        #pragma unroll
        for (int mt = 0; mt < 2; mt++){
            float2 fa = __half22float2(rhA[mt]);
            float2 fb = __half22float2(rhB[mt]);
            rs[mt][0] += fa.x + fa.y;
            rs[mt][1] += fb.x + fb.y;
        }
        __syncthreads();
    }

    int b = bh / NH, h = bh % NH;
    #pragma unroll
    for (int mt = 0; mt < 2; mt++){
        float r0 = rs[mt][0], r1 = rs[mt][1];
        r0 += __shfl_xor_sync(~0u, r0, 1); r0 += __shfl_xor_sync(~0u, r0, 2);
        r1 += __shfl_xor_sync(~0u, r1, 1); r1 += __shfl_xor_sync(~0u, r1, 2);
        float i0 = 1.f/r0, i1 = 1.f/r1;
        int qrow = q0 + wid*32 + mt*16 + (lane >> 2);
        #pragma unroll
        for (int dt = 0; dt < 8; dt++){
            int col = h*64 + dt*8 + 2*(lane & 3);
            float2 lo = __half22float2(*(__half2*)&o16[mt][dt][0]);
            float2 hi = __half22float2(*(__half2*)&o16[mt][dt][1]);
            *(uint32_t*)&av[(size_t)(b*SS + qrow)*DM + col]     = pack2(lo.x*i0, lo.y*i0);
            *(uint32_t*)&av[(size_t)(b*SS + qrow + 8)*DM + col] = pack2(hi.x*i1, hi.y*i1);
        }
    }
}

// ---------------- residual + scalar-affine norm: warp per 768-row ----------------
template<bool RELU, bool OUTF>
__global__ __launch_bounds__(256)
void norm_w(const __half* __restrict__ x1, const __half* __restrict__ x2,
            const float* __restrict__ scale, const float* __restrict__ bias,
            float* __restrict__ out, __half* __restrict__ oh)
{
    const int lane = threadIdx.x & 31, wid = threadIdx.x >> 5;
    const size_t row = (size_t)blockIdx.x*8 + wid;
    const uint2* p1 = (const uint2*)(x1 + row*DM);
    const uint2* p2 = (const uint2*)(x2 + row*DM);

    float4 v[6];
    float s = 0.f;
    #pragma unroll
    for (int c = 0; c < 6; c++){
        uint2 hp = p1[c*32 + lane];
        float2 a01 = __half22float2(*(__half2*)&hp.x);
        float2 a23 = __half22float2(*(__half2*)&hp.y);
        if (RELU){
            a01.x = fmaxf(a01.x,0.f); a01.y = fmaxf(a01.y,0.f);
            a23.x = fmaxf(a23.x,0.f); a23.y = fmaxf(a23.y,0.f);
        }
        uint2 h2 = p2[c*32 + lane];
        float2 b01 = __half22float2(*(__half2*)&h2.x);
        float2 b23 = __half22float2(*(__half2*)&h2.y);
        v[c].x = a01.x + b01.x; v[c].y = a01.y + b01.y;
        v[c].z = a23.x + b23.x; v[c].w = a23.y + b23.y;
        s += v[c].x + v[c].y + v[c].z + v[c].w;
    }
    #pragma unroll
    for (int m = 16; m > 0; m >>= 1) s += __shfl_xor_sync(~0u, s, m);
    float mean = s * (1.f/DM);
    float sq = 0.f;
    #pragma unroll
    for (int c = 0; c < 6; c++){
        float dx = v[c].x - mean, dy = v[c].y - mean, dz = v[c].z - mean, dw = v[c].w - mean;
        sq += dx*dx + dy*dy + dz*dz + dw*dw;
    }
    #pragma unroll
    for (int m = 16; m > 0; m >>= 1) sq += __shfl_xor_sync(~0u, sq, m);
    float inv_std = rsqrtf(sq * (1.f/DM));
    float sc = scale[0], bi = bias[0];
    #pragma unroll
    for (int c = 0; c < 6; c++){
        float4 o;
        o.x = (v[c].x - mean)*inv_std*sc + bi;
        o.y = (v[c].y - mean)*inv_std*sc + bi;
        o.z = (v[c].z - mean)*inv_std*sc + bi;
        o.w = (v[c].w - mean)*inv_std*sc + bi;
        if (OUTF){
            ((float4*)(out + row*DM))[c*32 + lane] = o;
        } else {
            uint2 hv = { pack2(o.x, o.y), pack2(o.z, o.w) };
            ((uint2*)(oh + row*DM))[c*32 + lane] = hv;
        }
    }
}

// ---------------- launch ----------------
extern "C" void kernel_launch(void* const* d_in, const int* in_sizes, int n_in,
                              void* d_out, int out_size)
{
    const float* base = (const float*)d_in[0];
    const float* Wqkv = (const float*)d_in[1];
    const float* bqkv = (const float*)d_in[2];
    const float* W1   = (const float*)d_in[3];
    const float* b1   = (const float*)d_in[4];
    const float* W2   = (const float*)d_in[5];
    const float* b2   = (const float*)d_in[6];
    const float* n1s  = (const float*)d_in[7];
    const float* n1b  = (const float*)d_in[8];
    const float* n2s  = (const float*)d_in[9];
    const float* n2b  = (const float*)d_in[10];
    float* out = (float*)d_out;

    __half *t1, *bh, *qh, *kh, *vt, *av, *hh, *wqT, *w1T, *w2T;
    cudaGetSymbolAddress((void**)&t1,  g_t1);
    cudaGetSymbolAddress((void**)&bh,  g_bh);
    cudaGetSymbolAddress((void**)&qh,  g_qh);
    cudaGetSymbolAddress((void**)&kh,  g_kh);
    cudaGetSymbolAddress((void**)&vt,  g_vt);
    cudaGetSymbolAddress((void**)&av,  g_av);
    cudaGetSymbolAddress((void**)&hh,  g_hh);
    cudaGetSymbolAddress((void**)&wqT, g_wqT);
    cudaGetSymbolAddress((void**)&w1T, g_w1T);
    cudaGetSymbolAddress((void**)&w2T, g_w2T);

    cudaFuncSetAttribute(gemm_h<DM3,DM,1>, cudaFuncAttributeMaxDynamicSharedMemorySize, 98304);
    cudaFuncSetAttribute(gemm_h<DM,DM,0>,  cudaFuncAttributeMaxDynamicSharedMemorySize, 98304);
    cudaFuncSetAttribute(attn_h,           cudaFuncAttributeMaxDynamicSharedMemorySize, 98304);

    prep<<<PREP_TOTAL, 256>>>((const float4*)base, (uint2*)bh, Wqkv, wqT, W1, w1T, W2, w2T);

    gemm_h<DM3,DM,1><<<dim3(DM3/128, MR/128), 256, 98304>>>(bh, wqT, bqkv, nullptr, qh, kh, vt);
    attn_h<<<dim3(SS/256, BB*NH), 256, 98304>>>(qh, kh, vt, av);
    gemm_h<DM,DM,0><<<dim3(DM/128, MR/128), 256, 98304>>>(av, w1T, b1, t1, nullptr, nullptr, nullptr);
    norm_w<false, false><<<MR/8, 256>>>(t1, bh, n1s, n1b, nullptr, hh);
    gemm_h<DM,DM,0><<<dim3(DM/128, MR/128), 256, 98304>>>(hh, w2T, b2, t1, nullptr, nullptr, nullptr);
    norm_w<true, true><<<MR/8, 256>>>(t1, hh, n2s, n2b, out, nullptr);
}

// round 16
// speedup vs baseline: 1.5301x; 1.5301x over previous
#include <cuda_runtime.h>
#include <cuda_fp16.h>
#include <math.h>
#include <stdint.h>

#define BB 4
#define SS 2048
#define DM 768
#define NH 12
#define HD 64
#define DM3 2304
#define MR (BB*SS)

// ---------------- scratch ----------------
__device__ __half g_t1 [(size_t)MR*DM];
__device__ __half g_bh [(size_t)MR*DM];
__device__ __half g_qh [(size_t)MR*DM];   // [b*NH+h][s][64], pre-scaled 0.125*log2e
__device__ __half g_kh [(size_t)MR*DM];
__device__ __half g_vt [(size_t)MR*DM];   // [b*NH+h][64][2048]  (V^T)
__device__ __half g_av [(size_t)MR*DM];
__device__ __half g_hh [(size_t)MR*DM];   // hidden (f16 only)
__device__ __half g_wqT[(size_t)DM3*DM];
__device__ __half g_w1T[(size_t)DM*DM];
__device__ __half g_w2T[(size_t)DM*DM];

// ---------------- helpers ----------------
__device__ __forceinline__ uint32_t smem_u32(const void* p){
    uint32_t a;
    asm("{ .reg .u64 t; cvta.to.shared.u64 t, %1; cvt.u32.u64 %0, t; }" : "=r"(a) : "l"(p));
    return a;
}
#define CPA(dst, src) asm volatile("cp.async.cg.shared.global [%0], [%1], 16;" :: "r"((uint32_t)(dst)), "l"(src) : "memory")
#define CPA_COMMIT() asm volatile("cp.async.commit_group;" ::: "memory")
#define CPA_WAIT0() asm volatile("cp.async.wait_group 0;" ::: "memory")
#define CPA_WAIT1() asm volatile("cp.async.wait_group 1;" ::: "memory")

__device__ __forceinline__ uint32_t swz(uint32_t o){ return o ^ ((o >> 3) & 0x70); }

__device__ __forceinline__ void ldsm4(uint32_t &r0, uint32_t &r1, uint32_t &r2, uint32_t &r3, uint32_t a){
    asm volatile("ldmatrix.sync.aligned.m8n8.x4.shared.b16 {%0,%1,%2,%3}, [%4];"
                 : "=r"(r0), "=r"(r1), "=r"(r2), "=r"(r3) : "r"(a));
}
__device__ __forceinline__ void mma16816(float* c, uint32_t a0, uint32_t a1, uint32_t a2, uint32_t a3,
                                         uint32_t b0, uint32_t b1){
    asm volatile("mma.sync.aligned.m16n8k16.row.col.f32.f16.f16.f32 "
                 "{%0,%1,%2,%3}, {%4,%5,%6,%7}, {%8,%9}, {%0,%1,%2,%3};"
                 : "+f"(c[0]), "+f"(c[1]), "+f"(c[2]), "+f"(c[3])
                 : "r"(a0), "r"(a1), "r"(a2), "r"(a3), "r"(b0), "r"(b1));
}
__device__ __forceinline__ void mma16816h(uint32_t* c, uint32_t a0, uint32_t a1, uint32_t a2, uint32_t a3,
                                          uint32_t b0, uint32_t b1){
    asm volatile("mma.sync.aligned.m16n8k16.row.col.f16.f16.f16.f16 "
                 "{%0,%1}, {%2,%3,%4,%5}, {%6,%7}, {%0,%1};"
                 : "+r"(c[0]), "+r"(c[1])
                 : "r"(a0), "r"(a1), "r"(a2), "r"(a3), "r"(b0), "r"(b1));
}
__device__ __forceinline__ uint32_t pack2(float a, float b){
    __half2 h = __floats2half2_rn(a, b);
    return *(uint32_t*)&h;
}
#define EX2IP(r) asm("ex2.approx.f16x2 %0, %0;" : "+r"(r))

// ---------------- merged prep ----------------
#define PREP_CB 1024
#define PREP_TQ ((DM3/32)*(DM/32))   // 1728
#define PREP_T1 ((DM/32)*(DM/32))    // 576
#define PREP_TOTAL (PREP_CB + PREP_TQ + 2*PREP_T1)

__device__ __forceinline__ void transp_tile(const float* __restrict__ W, __half* __restrict__ T,
                                            int K, int N, int n0, int k0, float (*s)[33]){
    int j = threadIdx.x & 31, i0 = threadIdx.x >> 5;
    #pragma unroll
    for (int l = 0; l < 4; l++){ int i = i0 + l*8; s[i][j] = W[(size_t)(k0+i)*N + n0 + j]; }
    __syncthreads();
    #pragma unroll
    for (int l = 0; l < 4; l++){
        int i = i0 + l*8;
        T[(size_t)(n0+i)*K + k0 + j] = __float2half_rn(s[j][i]);
    }
}

__global__ __launch_bounds__(256)
void prep(const float4* __restrict__ base4, uint2* __restrict__ bh4,
          const float* __restrict__ Wqkv, __half* __restrict__ wqT,
          const float* __restrict__ W1,   __half* __restrict__ w1T,
          const float* __restrict__ W2,   __half* __restrict__ w2T)
{
    __shared__ float s[32][33];
    int b = blockIdx.x;
    if (b < PREP_CB){
        const int n4 = MR*DM/4;
        for (int i = b*256 + threadIdx.x; i < n4; i += PREP_CB*256){
            float4 v = base4[i];
            uint2 o = { pack2(v.x, v.y), pack2(v.z, v.w) };
            bh4[i] = o;
        }
    } else if (b < PREP_CB + PREP_TQ){
        int idx = b - PREP_CB;
        transp_tile(Wqkv, wqT, DM, DM3, (idx % (DM3/32))*32, (idx / (DM3/32))*32, s);
    } else if (b < PREP_CB + PREP_TQ + PREP_T1){
        int idx = b - PREP_CB - PREP_TQ;
        transp_tile(W1, w1T, DM, DM, (idx % (DM/32))*32, (idx / (DM/32))*32, s);
    } else {
        int idx = b - PREP_CB - PREP_TQ - PREP_T1;
        transp_tile(W2, w2T, DM, DM, (idx % (DM/32))*32, (idx / (DM/32))*32, s);
    }
}

// ---------------- GEMM: A[M][K]@B[N][K]^T + bias, fp32 accum, 128x128 tiles ----------------
// 2-stage cp.async pipeline, load issued BEFORE the wait (prefetch lead time is load-bearing).
// MODE 0: C f16 [M][N].  MODE 1: fused QKV epilogue.
template<int N, int K, int MODE>
__global__ __launch_bounds__(256, 2)
void gemm_h(const __half* __restrict__ A, const __half* __restrict__ B,
            const float* __restrict__ bias, __half* __restrict__ C,
            __half* __restrict__ qh, __half* __restrict__ kh, __half* __restrict__ vt)
{
    extern __shared__ char sm[];
    const uint32_t sb = smem_u32(sm);
    const int tid = threadIdx.x, lane = tid & 31, wid = tid >> 5;
    const int wm = (wid & 1)*64, wn = (wid >> 1)*32;
    const int m0 = blockIdx.y*128, n0 = blockIdx.x*128;
    const int NC = K/64;

    float acc[4][4][4] = {};

    auto load = [&](int c, int s){
        uint32_t sa = sb + s*32768, sbm = sa + 16384;
        int k0 = c*64;
        #pragma unroll
        for (int l = 0; l < 4; l++){
            int idx = tid + l*256;
            int r = idx >> 3, c16 = idx & 7;
            uint32_t o = swz((uint32_t)(r*128 + c16*16));
            CPA(sa  + o, (const char*)(A + (size_t)(m0+r)*K + k0 + c16*8));
            CPA(sbm + o, (const char*)(B + (size_t)(n0+r)*K + k0 + c16*8));
        }
        CPA_COMMIT();
    };

    load(0, 0);
    #pragma unroll
    for (int c = 0; c < NC; c++){
        int s = c & 1;
        if (c+1 < NC) load(c+1, 1-s);
        if (c+1 < NC) CPA_WAIT1(); else CPA_WAIT0();
        __syncthreads();
        uint32_t sa = sb + s*32768, sbm = sa + 16384;
        #pragma unroll
        for (int ks = 0; ks < 4; ks++){
            uint32_t a[4][4];
            #pragma unroll
            for (int mt = 0; mt < 4; mt++)
                ldsm4(a[mt][0], a[mt][1], a[mt][2], a[mt][3],
                      sa + swz((uint32_t)((wm + mt*16 + (lane & 15))*128 + (ks*16 + ((lane >> 4) << 3))*2)));
            #pragma unroll
            for (int np = 0; np < 2; np++){
                uint32_t b0, b1, b2, b3;
                int n  = wn + np*16 + ((lane >> 4) << 3) + (lane & 7);
                int kh2 = ks*16 + ((lane >> 3) & 1)*8;
                ldsm4(b0, b1, b2, b3, sbm + swz((uint32_t)(n*128 + kh2*2)));
                #pragma unroll
                for (int mt = 0; mt < 4; mt++){
                    mma16816(acc[mt][np*2],   a[mt][0], a[mt][1], a[mt][2], a[mt][3], b0, b1);
                    mma16816(acc[mt][np*2+1], a[mt][0], a[mt][1], a[mt][2], a[mt][3], b2, b3);
                }
            }
        }
        __syncthreads();
    }

    if (MODE == 0){
        #pragma unroll
        for (int mt = 0; mt < 4; mt++){
            int row = m0 + wm + mt*16 + (lane >> 2);
            #pragma unroll
            for (int nt = 0; nt < 4; nt++){
                int col = n0 + wn + nt*8 + 2*(lane & 3);
                float2 bi = *(const float2*)&bias[col];
                *(uint32_t*)&C[(size_t)row*N + col]     = pack2(acc[mt][nt][0] + bi.x, acc[mt][nt][1] + bi.y);
                *(uint32_t*)&C[(size_t)(row+8)*N + col] = pack2(acc[mt][nt][2] + bi.x, acc[mt][nt][3] + bi.y);
            }
        }
    } else {
        const int b  = m0 >> 11;
        const int s0 = m0 & 2047;
        const int region = n0 / DM;
        const int h0 = (n0 % DM) >> 6;
        if (region < 2){
            const float sc = (region == 0) ? 0.125f*1.44269504f : 1.f;
            __half* dst = (region == 0) ? qh : kh;
            #pragma unroll
            for (int mt = 0; mt < 4; mt++){
                int r = wm + mt*16 + (lane >> 2);
                #pragma unroll
                for (int nt = 0; nt < 4; nt++){
                    int cl = wn + nt*8 + 2*(lane & 3);
                    float2 bi = *(const float2*)&bias[n0 + cl];
                    int h = h0 + (cl >> 6), d = cl & 63;
                    size_t a0 = ((size_t)(b*NH + h)*SS + s0 + r)*64 + d;
                    *(uint32_t*)&dst[a0]        = pack2((acc[mt][nt][0]+bi.x)*sc, (acc[mt][nt][1]+bi.y)*sc);
                    *(uint32_t*)&dst[a0 + 8*64] = pack2((acc[mt][nt][2]+bi.x)*sc, (acc[mt][nt][3]+bi.y)*sc);
                }
            }
        } else {
            __half* st = (__half*)sm;
            #pragma unroll
            for (int mt = 0; mt < 4; mt++){
                int r = wm + mt*16 + (lane >> 2);
                #pragma unroll
                for (int nt = 0; nt < 4; nt++){
                    int cl = wn + nt*8 + 2*(lane & 3);
                    float2 bi = *(const float2*)&bias[n0 + cl];
                    st[(cl+0)*136 + r]     = __float2half_rn(acc[mt][nt][0] + bi.x);
                    st[(cl+1)*136 + r]     = __float2half_rn(acc[mt][nt][1] + bi.y);
                    st[(cl+0)*136 + r + 8] = __float2half_rn(acc[mt][nt][2] + bi.x);
                    st[(cl+1)*136 + r + 8] = __float2half_rn(acc[mt][nt][3] + bi.y);
                }
            }
            __syncthreads();
            #pragma unroll
            for (int l = 0; l < 8; l++){
                int idx = tid + l*256;
                int d = idx >> 4, rc = idx & 15;
                uint4 v = *(const uint4*)&st[d*136 + rc*8];
                int h = h0 + (d >> 6), dl = d & 63;
                *(uint4*)&vt[((size_t)(b*NH + h)*64 + dl)*SS + s0 + rc*8] = v;
            }
        }
    }
}

// ---------------- attention: CTA = (256-query tile, bh); 8 warps x 32 q-rows, f16 accum ----------------
__global__ __launch_bounds__(256, 2)
void attn_h(const __half* __restrict__ Q, const __half* __restrict__ Kh,
            const __half* __restrict__ Vt, __half* __restrict__ av)
{
    extern __shared__ char sm[];
    const uint32_t sb = smem_u32(sm);
    const uint32_t SQ = sb;            // 32KB (256 q rows)
    const uint32_t SK = sb + 32768;    // 2 x 16KB
    const uint32_t SV = sb + 65536;    // 2 x 16KB
    const int tid = threadIdx.x, lane = tid & 31, wid = tid >> 5;
    const int q0 = blockIdx.x*256, bh = blockIdx.y;
    const __half* Qp = Q  + (size_t)bh*SS*64 + (size_t)q0*64;
    const __half* Kp = Kh + (size_t)bh*SS*64;
    const __half* Vp = Vt + (size_t)bh*64*SS;

    #pragma unroll
    for (int l = 0; l < 8; l++){
        int idx = tid + l*256; int r = idx >> 3, c = idx & 7;
        CPA(SQ + swz((uint32_t)(r*128 + c*16)), (const char*)(Qp + r*64 + c*8));
    }
    #pragma unroll
    for (int l = 0; l < 4; l++){
        int idx = tid + l*256; int r = idx >> 3, c = idx & 7;
        CPA(SK + swz((uint32_t)(r*128 + c*16)), (const char*)(Kp + r*64 + c*8));
    }
    #pragma unroll
    for (int l = 0; l < 4; l++){
        int idx = tid + l*256; int d = idx >> 4, c = idx & 15;
        CPA(SV + (c >> 3)*8192 + swz((uint32_t)(d*128 + (c & 7)*16)), (const char*)(Vp + (size_t)d*SS + c*8));
    }
    CPA_COMMIT();

    uint32_t o16[2][8][2] = {};
    float rs[2][2] = {};
    uint32_t qf[2][4][4];

    for (int t = 0; t < 16; t++){
        int s = t & 1;
        if (t+1 < 16){
            const __half* Kn = Kp + (size_t)(t+1)*128*64;
            #pragma unroll
            for (int l = 0; l < 4; l++){
                int idx = tid + l*256; int r = idx >> 3, c = idx & 7;
                CPA(SK + (1-s)*16384 + swz((uint32_t)(r*128 + c*16)), (const char*)(Kn + r*64 + c*8));
            }
            #pragma unroll
            for (int l = 0; l < 4; l++){
                int idx = tid + l*256; int d = idx >> 4, c = idx & 15;
                CPA(SV + (1-s)*16384 + (c >> 3)*8192 + swz((uint32_t)(d*128 + (c & 7)*16)),
                    (const char*)(Vp + (size_t)d*SS + (t+1)*128 + c*8));
            }
            CPA_COMMIT();
            CPA_WAIT1();
        } else CPA_WAIT0();
        __syncthreads();

        if (t == 0){
            #pragma unroll
            for (int mt = 0; mt < 2; mt++)
                #pragma unroll
                for (int ks = 0; ks < 4; ks++)
                    ldsm4(qf[mt][ks][0], qf[mt][ks][1], qf[mt][ks][2], qf[mt][ks][3],
                          SQ + swz((uint32_t)((wid*32 + mt*16 + (lane & 15))*128 + (ks*16 + ((lane >> 4) << 3))*2)));
        }

        uint32_t sk = SK + s*16384, sv = SV + s*16384;
        __half2 rhA[2], rhB[2];
        rhA[0] = rhA[1] = rhB[0] = rhB[1] = __floats2half2_rn(0.f, 0.f);
        #pragma unroll
        for (int np = 0; np < 8; np++){
            uint32_t sc[2][2][2] = {};
            #pragma unroll
            for (int ks = 0; ks < 4; ks++){
                uint32_t b0, b1, b2, b3;
                int n  = np*16 + ((lane >> 4) << 3) + (lane & 7);
                int kh = ks*16 + ((lane >> 3) & 1)*8;
                ldsm4(b0, b1, b2, b3, sk + swz((uint32_t)(n*128 + kh*2)));
                #pragma unroll
                for (int mt = 0; mt < 2; mt++){
                    mma16816h(sc[mt][0], qf[mt][ks][0], qf[mt][ks][1], qf[mt][ks][2], qf[mt][ks][3], b0, b1);
                    mma16816h(sc[mt][1], qf[mt][ks][0], qf[mt][ks][1], qf[mt][ks][2], qf[mt][ks][3], b2, b3);
                }
            }
            #pragma unroll
            for (int mt = 0; mt < 2; mt++){
                EX2IP(sc[mt][0][0]); EX2IP(sc[mt][0][1]);
                EX2IP(sc[mt][1][0]); EX2IP(sc[mt][1][1]);
                rhA[mt] = __hadd2(rhA[mt], __hadd2(*(__half2*)&sc[mt][0][0], *(__half2*)&sc[mt][1][0]));
                rhB[mt] = __hadd2(rhB[mt], __hadd2(*(__half2*)&sc[mt][0][1], *(__half2*)&sc[mt][1][1]));
            }
            #pragma unroll
            for (int dp = 0; dp < 4; dp++){
                uint32_t b0, b1, b2, b3;
                int d   = dp*16 + ((lane >> 4) << 3) + (lane & 7);
                int key = np*16 + ((lane >> 3) & 1)*8;
                ldsm4(b0, b1, b2, b3, sv + (key >> 6)*8192 + swz((uint32_t)(d*128 + (key & 63)*2)));
                #pragma unroll
                for (int mt = 0; mt < 2; mt++){
                    mma16816h(o16[mt][dp*2],   sc[mt][0][0], sc[mt][0][1], sc[mt][1][0], sc[mt][1][1], b0, b1);
                    mma16816h(o16[mt][dp*2+1], sc[mt][0][0], sc[mt][0][1], sc[mt][1][0], sc[mt][1][1], b2, b3);
                }
            }
        }
        #pragma unroll
        for (int mt = 0; mt < 2; mt++){
            float2 fa = __half22float2(rhA[mt]);
            float2 fb = __half22float2(rhB[mt]);
            rs[mt][0] += fa.x + fa.y;
            rs[mt][1] += fb.x + fb.y;
        }
        __syncthreads();
    }

    int b = bh / NH, h = bh % NH;
    #pragma unroll
    for (int mt = 0; mt < 2; mt++){
        float r0 = rs[mt][0], r1 = rs[mt][1];
        r0 += __shfl_xor_sync(~0u, r0, 1); r0 += __shfl_xor_sync(~0u, r0, 2);
        r1 += __shfl_xor_sync(~0u, r1, 1); r1 += __shfl_xor_sync(~0u, r1, 2);
        float i0 = 1.f/r0, i1 = 1.f/r1;
        int qrow = q0 + wid*32 + mt*16 + (lane >> 2);
        #pragma unroll
        for (int dt = 0; dt < 8; dt++){
            int col = h*64 + dt*8 + 2*(lane & 3);
            float2 lo = __half22float2(*(__half2*)&o16[mt][dt][0]);
            float2 hi = __half22float2(*(__half2*)&o16[mt][dt][1]);
            *(uint32_t*)&av[(size_t)(b*SS + qrow)*DM + col]     = pack2(lo.x*i0, lo.y*i0);
            *(uint32_t*)&av[(size_t)(b*SS + qrow + 8)*DM + col] = pack2(hi.x*i1, hi.y*i1);
        }
    }
}

// ---------------- residual + scalar-affine norm: warp per 768-row ----------------
template<bool RELU, bool OUTF>
__global__ __launch_bounds__(256)
void norm_w(const __half* __restrict__ x1, const __half* __restrict__ x2,
            const float* __restrict__ scale, const float* __restrict__ bias,
            float* __restrict__ out, __half* __restrict__ oh)
{
    const int lane = threadIdx.x & 31, wid = threadIdx.x >> 5;
    const size_t row = (size_t)blockIdx.x*8 + wid;
    const uint2* p1 = (const uint2*)(x1 + row*DM);
    const uint2* p2 = (const uint2*)(x2 + row*DM);

    float4 v[6];
    float s = 0.f;
    #pragma unroll
    for (int c = 0; c < 6; c++){
        uint2 hp = p1[c*32 + lane];
        float2 a01 = __half22float2(*(__half2*)&hp.x);
        float2 a23 = __half22float2(*(__half2*)&hp.y);
        if (RELU){
            a01.x = fmaxf(a01.x,0.f); a01.y = fmaxf(a01.y,0.f);
            a23.x = fmaxf(a23.x,0.f); a23.y = fmaxf(a23.y,0.f);
        }
        uint2 h2 = p2[c*32 + lane];
        float2 b01 = __half22float2(*(__half2*)&h2.x);
        float2 b23 = __half22float2(*(__half2*)&h2.y);
        v[c].x = a01.x + b01.x; v[c].y = a01.y + b01.y;
        v[c].z = a23.x + b23.x; v[c].w = a23.y + b23.y;
        s += v[c].x + v[c].y + v[c].z + v[c].w;
    }
    #pragma unroll
    for (int m = 16; m > 0; m >>= 1) s += __shfl_xor_sync(~0u, s, m);
    float mean = s * (1.f/DM);
    float sq = 0.f;
    #pragma unroll
    for (int c = 0; c < 6; c++){
        float dx = v[c].x - mean, dy = v[c].y - mean, dz = v[c].z - mean, dw = v[c].w - mean;
        sq += dx*dx + dy*dy + dz*dz + dw*dw;
    }
    #pragma unroll
    for (int m = 16; m > 0; m >>= 1) sq += __shfl_xor_sync(~0u, sq, m);
    float inv_std = rsqrtf(sq * (1.f/DM));
    float sc = scale[0], bi = bias[0];
    #pragma unroll
    for (int c = 0; c < 6; c++){
        float4 o;
        o.x = (v[c].x - mean)*inv_std*sc + bi;
        o.y = (v[c].y - mean)*inv_std*sc + bi;
        o.z = (v[c].z - mean)*inv_std*sc + bi;
        o.w = (v[c].w - mean)*inv_std*sc + bi;
        if (OUTF){
            ((float4*)(out + row*DM))[c*32 + lane] = o;
        } else {
            uint2 hv = { pack2(o.x, o.y), pack2(o.z, o.w) };
            ((uint2*)(oh + row*DM))[c*32 + lane] = hv;
        }
    }
}

// ---------------- launch ----------------
extern "C" void kernel_launch(void* const* d_in, const int* in_sizes, int n_in,
                              void* d_out, int out_size)
{
    const float* base = (const float*)d_in[0];
    const float* Wqkv = (const float*)d_in[1];
    const float* bqkv = (const float*)d_in[2];
    const float* W1   = (const float*)d_in[3];
    const float* b1   = (const float*)d_in[4];
    const float* W2   = (const float*)d_in[5];
    const float* b2   = (const float*)d_in[6];
    const float* n1s  = (const float*)d_in[7];
    const float* n1b  = (const float*)d_in[8];
    const float* n2s  = (const float*)d_in[9];
    const float* n2b  = (const float*)d_in[10];
    float* out = (float*)d_out;

    __half *t1, *bh, *qh, *kh, *vt, *av, *hh, *wqT, *w1T, *w2T;
    cudaGetSymbolAddress((void**)&t1,  g_t1);
    cudaGetSymbolAddress((void**)&bh,  g_bh);
    cudaGetSymbolAddress((void**)&qh,  g_qh);
    cudaGetSymbolAddress((void**)&kh,  g_kh);
    cudaGetSymbolAddress((void**)&vt,  g_vt);
    cudaGetSymbolAddress((void**)&av,  g_av);
    cudaGetSymbolAddress((void**)&hh,  g_hh);
    cudaGetSymbolAddress((void**)&wqT, g_wqT);
    cudaGetSymbolAddress((void**)&w1T, g_w1T);
    cudaGetSymbolAddress((void**)&w2T, g_w2T);

    cudaFuncSetAttribute(gemm_h<DM3,DM,1>, cudaFuncAttributeMaxDynamicSharedMemorySize, 65536);
    cudaFuncSetAttribute(gemm_h<DM,DM,0>,  cudaFuncAttributeMaxDynamicSharedMemorySize, 65536);
    cudaFuncSetAttribute(attn_h,           cudaFuncAttributeMaxDynamicSharedMemorySize, 98304);

    prep<<<PREP_TOTAL, 256>>>((const float4*)base, (uint2*)bh, Wqkv, wqT, W1, w1T, W2, w2T);

    gemm_h<DM3,DM,1><<<dim3(DM3/128, MR/128), 256, 65536>>>(bh, wqT, bqkv, nullptr, qh, kh, vt);
    attn_h<<<dim3(SS/256, BB*NH), 256, 98304>>>(qh, kh, vt, av);
    gemm_h<DM,DM,0><<<dim3(DM/128, MR/128), 256, 65536>>>(av, w1T, b1, t1, nullptr, nullptr, nullptr);
    norm_w<false, false><<<MR/8, 256>>>(t1, bh, n1s, n1b, nullptr, hh);
    gemm_h<DM,DM,0><<<dim3(DM/128, MR/128), 256, 65536>>>(hh, w2T, b2, t1, nullptr, nullptr, nullptr);
    norm_w<true, true><<<MR/8, 256>>>(t1, hh, n2s, n2b, out, nullptr);
}